// round 12
// baseline (speedup 1.0000x reference)
#include <cuda_runtime.h>
#include <stdint.h>

#define N_NODES 100000
#define N_EDGES 800000
#define HIDDEN  128

// ---------------- scratch (static device memory; no allocation) -------------
__device__ float g_S1[(size_t)N_NODES * HIDDEN];
__device__ float g_S2[(size_t)N_NODES * HIDDEN];
__device__ int   g_d1[N_NODES];
__device__ int   g_d2[N_NODES];
// pre-splatted weights: per src, float4 #(k*64 + (q&1)*32 + q/2) =
//   (W[2q][k], W[2q][k], W[2q+1][k], W[2q+1][k])   for col-group q=0..63
__device__ float g_Wsp[3][128 * 256];

// ---------------- helpers ---------------------------------------------------
__device__ __forceinline__ float2 unpack2(unsigned long long v) {
    float2 f;
    asm("mov.b64 {%0, %1}, %2;" : "=f"(f.x), "=f"(f.y) : "l"(v));
    return f;
}
__device__ __forceinline__ void fma2(unsigned long long& acc,
                                     unsigned long long a,
                                     unsigned long long b) {
    asm("fma.rn.f32x2 %0, %1, %2, %0;" : "+l"(acc) : "l"(a), "l"(b));
}

// ---------------- kernel 1: zero scratch ------------------------------------
__global__ void zero_kernel() {
    size_t tid    = (size_t)blockIdx.x * blockDim.x + threadIdx.x;
    size_t stride = (size_t)gridDim.x * blockDim.x;
    const size_t n4 = (size_t)N_NODES * HIDDEN / 4;
    float4 z = make_float4(0.f, 0.f, 0.f, 0.f);
    for (size_t j = tid; j < n4; j += stride) {
        ((float4*)g_S1)[j] = z;
        ((float4*)g_S2)[j] = z;
    }
    for (size_t j = tid; j < N_NODES; j += stride) {
        g_d1[j] = 0;
        g_d2[j] = 0;
    }
}

// ---------------- kernel 1b: splat weights into paired layout ---------------
__global__ void splat_kernel(const float* __restrict__ Ww,
                             const float* __restrict__ Wsw,
                             const float* __restrict__ Wtw) {
    int idx = blockIdx.x * 256 + threadIdx.x;       // 0..24575
    if (idx >= 3 * 128 * 64) return;
    int src = idx / (128 * 64);
    int rem = idx - src * (128 * 64);
    int q   = rem >> 7;          // col group 0..63 (cols 2q, 2q+1 of splat pairs)
    int k   = rem & 127;         // k index (consecutive lanes -> coalesced reads)
    const float* W = (src == 0) ? Ww : (src == 1) ? Wsw : Wtw;
    float w0 = W[(2 * q) * HIDDEN + k];
    float w1 = W[(2 * q + 1) * HIDDEN + k];
    int pos = (q & 1) * 32 + (q >> 1);
    ((float4*)g_Wsp[src])[k * 64 + pos] = make_float4(w0, w0, w1, w1);
}

// ---------------- kernel 2: fused edge aggregation (one warp per edge) ------
__global__ void __launch_bounds__(256) edge_kernel(const float* __restrict__ h,
                                                   const int*   __restrict__ esrc,
                                                   const int*   __restrict__ edst) {
    int warp = (blockIdx.x * blockDim.x + threadIdx.x) >> 5;
    int lane = threadIdx.x & 31;
    if (warp >= N_EDGES) return;

    int s = esrc[warp];
    int d = edst[warp];

    float4 vd = ((const float4*)(h + (size_t)d * HIDDEN))[lane];
    float4 vs = ((const float4*)(h + (size_t)s * HIDDEN))[lane];

    atomicAdd(((float4*)(g_S1 + (size_t)s * HIDDEN)) + lane, vd);
    atomicAdd(((float4*)(g_S2 + (size_t)d * HIDDEN)) + lane, vs);

    if (lane == 0)      atomicAdd(&g_d1[s], 1);
    else if (lane == 1) atomicAdd(&g_d2[d], 1);
}

// ---------------- kernel 3: fused GEMM + bias + relu ------------------------
// Same geometry as the measured-best core (64x128 tile, 256 thr, 8x4 thread
// tile of f32x2 accs). W now staged from the pre-splatted layout: staging is
// an identity copy (coalesced LDG, conflict-free STS) and each kk needs only
// 2 conflict-free LDS.128 for W with ZERO pack-MOVs.
__global__ void __launch_bounds__(256)
gemm_kernel(const float* __restrict__ h,
            const float* __restrict__ Wb,
            const float* __restrict__ Wsb,
            const float* __restrict__ Wtb,
            float* __restrict__ out) {
    __shared__ float As[32][68];                     //  8.7 KB
    __shared__ __align__(16) float4 Wsf[32 * 64];    // 32.0 KB (splat pairs)

    const int tid = threadIdx.x;
    const int tx  = tid & 31;       // cols tx*4 .. tx*4+3
    const int ty  = tid >> 5;       // rows ty*8 .. ty*8+7
    const int row0 = blockIdx.x * 64;

    const float* Alist[3];
    Alist[0] = g_S1; Alist[1] = h; Alist[2] = g_S2;

    // per-thread fixed A staging coordinates
    int ar[2], ag[2], arow_ok[2];
#pragma unroll
    for (int j = 0; j < 2; ++j) {
        int lin = tid + j * 256;
        ar[j] = lin >> 3;                 // 0..63
        ag[j] = lin & 7;
        arow_ok[j] = (row0 + ar[j]) < N_NODES;
    }

    unsigned long long acc[4][4];
#pragma unroll
    for (int p = 0; p < 4; ++p)
#pragma unroll
        for (int c = 0; c < 4; ++c) acc[p][c] = 0ull;

    float4 pa[2], pw[8];

    // prefetch chunk 0
    {
        const float* A = Alist[0];
        const float4* Wsp = (const float4*)g_Wsp[0];
#pragma unroll
        for (int j = 0; j < 2; ++j) {
            pa[j] = make_float4(0.f, 0.f, 0.f, 0.f);
            if (arow_ok[j])
                pa[j] = *(const float4*)(A + (size_t)(row0 + ar[j]) * HIDDEN + ag[j] * 4);
        }
#pragma unroll
        for (int j = 0; j < 8; ++j)
            pw[j] = Wsp[tid + j * 256];
    }

#pragma unroll 1
    for (int chunk = 0; chunk < 12; ++chunk) {
        __syncthreads();
        // store prefetched tiles
#pragma unroll
        for (int j = 0; j < 2; ++j) {
            int kk = ag[j] * 4, r = ar[j];
            As[kk + 0][r] = pa[j].x;
            As[kk + 1][r] = pa[j].y;
            As[kk + 2][r] = pa[j].z;
            As[kk + 3][r] = pa[j].w;
        }
#pragma unroll
        for (int j = 0; j < 8; ++j)
            Wsf[tid + j * 256] = pw[j];           // identity copy, conflict-free
        __syncthreads();

        // prefetch next chunk
        if (chunk < 11) {
            int nc   = chunk + 1;
            int sidx = nc >> 2;
            int k0   = (nc & 3) * 32;
            const float* A = Alist[sidx];
            const float4* Wsp = ((const float4*)g_Wsp[sidx]) + k0 * 64;
#pragma unroll
            for (int j = 0; j < 2; ++j) {
                pa[j] = make_float4(0.f, 0.f, 0.f, 0.f);
                if (arow_ok[j])
                    pa[j] = *(const float4*)(A + (size_t)(row0 + ar[j]) * HIDDEN + k0 + ag[j] * 4);
            }
#pragma unroll
            for (int j = 0; j < 8; ++j)
                pw[j] = Wsp[tid + j * 256];
        }

        // compute: per kk, 4 LDS.128 + 16 FFMA2, no MOVs
        const ulonglong2* Wsu = (const ulonglong2*)Wsf;
#pragma unroll
        for (int kk = 0; kk < 32; ++kk) {
            ulonglong2 a01 = *(const ulonglong2*)&As[kk][ty * 8];       // rows 0-3
            ulonglong2 a23 = *(const ulonglong2*)&As[kk][ty * 8 + 4];   // rows 4-7
            ulonglong2 wA = Wsu[kk * 64 + tx];        // splat cols 4tx, 4tx+1
            ulonglong2 wB = Wsu[kk * 64 + 32 + tx];   // splat cols 4tx+2, 4tx+3

            fma2(acc[0][0], a01.x, wA.x); fma2(acc[0][1], a01.x, wA.y);
            fma2(acc[0][2], a01.x, wB.x); fma2(acc[0][3], a01.x, wB.y);
            fma2(acc[1][0], a01.y, wA.x); fma2(acc[1][1], a01.y, wA.y);
            fma2(acc[1][2], a01.y, wB.x); fma2(acc[1][3], a01.y, wB.y);
            fma2(acc[2][0], a23.x, wA.x); fma2(acc[2][1], a23.x, wA.y);
            fma2(acc[2][2], a23.x, wB.x); fma2(acc[2][3], a23.x, wB.y);
            fma2(acc[3][0], a23.y, wA.x); fma2(acc[3][1], a23.y, wA.y);
            fma2(acc[3][2], a23.y, wB.x); fma2(acc[3][3], a23.y, wB.y);
        }
    }

    // epilogue: degree-scaled bias + relu
    const int colbase = tx * 4;
    float4 bw  = *(const float4*)(Wb  + colbase);
    float4 bs  = *(const float4*)(Wsb + colbase);
    float4 bt  = *(const float4*)(Wtb + colbase);

#pragma unroll
    for (int p = 0; p < 4; ++p) {
        int re = row0 + ty * 8 + 2 * p;
        if (re >= N_NODES) break;
        float2 v0 = unpack2(acc[p][0]);
        float2 v1 = unpack2(acc[p][1]);
        float2 v2 = unpack2(acc[p][2]);
        float2 v3 = unpack2(acc[p][3]);

        {
            float f1 = (float)g_d1[re];
            float f2 = (float)g_d2[re];
            float4 o;
            o.x = fmaxf(v0.x + f1 * bw.x + bs.x + f2 * bt.x, 0.f);
            o.y = fmaxf(v1.x + f1 * bw.y + bs.y + f2 * bt.y, 0.f);
            o.z = fmaxf(v2.x + f1 * bw.z + bs.z + f2 * bt.z, 0.f);
            o.w = fmaxf(v3.x + f1 * bw.w + bs.w + f2 * bt.w, 0.f);
            *(float4*)(out + (size_t)re * HIDDEN + colbase) = o;
        }
        int ro = re + 1;
        if (ro < N_NODES) {
            float f1 = (float)g_d1[ro];
            float f2 = (float)g_d2[ro];
            float4 o;
            o.x = fmaxf(v0.y + f1 * bw.x + bs.x + f2 * bt.x, 0.f);
            o.y = fmaxf(v1.y + f1 * bw.y + bs.y + f2 * bt.y, 0.f);
            o.z = fmaxf(v2.y + f1 * bw.z + bs.z + f2 * bt.z, 0.f);
            o.w = fmaxf(v3.y + f1 * bw.w + bs.w + f2 * bt.w, 0.f);
            *(float4*)(out + (size_t)ro * HIDDEN + colbase) = o;
        }
    }
}

// ---------------- launch -----------------------------------------------------
extern "C" void kernel_launch(void* const* d_in, const int* in_sizes, int n_in,
                              void* d_out, int out_size) {
    const float* h    = (const float*)d_in[0];
    const int*   esrc = (const int*)  d_in[1];
    const int*   edst = (const int*)  d_in[2];
    const float* Ww   = (const float*)d_in[3];
    const float* Wb   = (const float*)d_in[4];
    const float* Wsw  = (const float*)d_in[5];
    const float* Wsb  = (const float*)d_in[6];
    const float* Wtw  = (const float*)d_in[7];
    const float* Wtb  = (const float*)d_in[8];
    float* out = (float*)d_out;

    zero_kernel<<<2048, 256>>>();
    splat_kernel<<<(3 * 128 * 64 + 255) / 256, 256>>>(Ww, Wsw, Wtw);
    edge_kernel<<<(N_EDGES + 7) / 8, 256>>>(h, esrc, edst);
    gemm_kernel<<<(N_NODES + 63) / 64, 256>>>(h, Wb, Wsb, Wtb, out);
}

// round 13
// speedup vs baseline: 1.1052x; 1.1052x over previous
#include <cuda_runtime.h>
#include <stdint.h>

#define N_NODES 100000
#define N_EDGES 800000
#define HIDDEN  128

// ---------------- scratch (static device memory; no allocation) -------------
__device__ float g_S1[(size_t)N_NODES * HIDDEN];   // sum over edges (i,j) of h[j], indexed by i
__device__ float g_S2[(size_t)N_NODES * HIDDEN];   // sum over edges (i,j) of h[i], indexed by j
__device__ int   g_d1[N_NODES];                    // out-degree
__device__ int   g_d2[N_NODES];                    // in-degree

// ---------------- helpers ---------------------------------------------------
__device__ __forceinline__ unsigned long long pack2(float lo, float hi) {
    unsigned long long r;
    asm("mov.b64 %0, {%1, %2};" : "=l"(r) : "f"(lo), "f"(hi));
    return r;
}
__device__ __forceinline__ float2 unpack2(unsigned long long v) {
    float2 f;
    asm("mov.b64 {%0, %1}, %2;" : "=f"(f.x), "=f"(f.y) : "l"(v));
    return f;
}
__device__ __forceinline__ void fma2(unsigned long long& acc,
                                     unsigned long long a,
                                     unsigned long long b) {
    asm("fma.rn.f32x2 %0, %1, %2, %0;" : "+l"(acc) : "l"(a), "l"(b));
}

// ---------------- kernel 1: fused edge aggregation (one warp per edge) ------
__global__ void __launch_bounds__(256) edge_kernel(const float* __restrict__ h,
                                                   const int*   __restrict__ esrc,
                                                   const int*   __restrict__ edst) {
    int warp = (blockIdx.x * blockDim.x + threadIdx.x) >> 5;
    int lane = threadIdx.x & 31;
    if (warp >= N_EDGES) return;

    int s = esrc[warp];
    int d = edst[warp];

    // gather h[d], h[s]  (32 lanes x float4 = 128 floats each)
    float4 vd = ((const float4*)(h + (size_t)d * HIDDEN))[lane];
    float4 vs = ((const float4*)(h + (size_t)s * HIDDEN))[lane];

    // scatter-add with vector atomics (sm_90+)
    atomicAdd(((float4*)(g_S1 + (size_t)s * HIDDEN)) + lane, vd);
    atomicAdd(((float4*)(g_S2 + (size_t)d * HIDDEN)) + lane, vs);

    if (lane == 0)      atomicAdd(&g_d1[s], 1);
    else if (lane == 1) atomicAdd(&g_d2[d], 1);
}

// ---------------- kernel 2: fused GEMM + bias + relu ------------------------
// out[i] = relu( S1[i]@Ww^T + d1[i]*Wb + h[i]@Wsw^T + Wsb + S2[i]@Wtw^T + d2[i]*Wtb )
// Tile: 64 rows x 128 cols per block, 256 threads, thread tile 8 rows x 4 cols.
// Accumulators are f32x2 pairs over adjacent rows -> fma.rn.f32x2.
// This is the measured-best core (247.4us); do not restructure.
__global__ void __launch_bounds__(256) gemm_kernel(const float* __restrict__ h,
                                                   const float* __restrict__ Ww,
                                                   const float* __restrict__ Wb,
                                                   const float* __restrict__ Wsw,
                                                   const float* __restrict__ Wsb,
                                                   const float* __restrict__ Wtw,
                                                   const float* __restrict__ Wtb,
                                                   float* __restrict__ out) {
    __shared__ float As[32][68];    // [k][row]
    __shared__ float Ws[32][132];   // [k][col]

    const int tid = threadIdx.x;
    const int tx  = tid & 31;       // col group: cols tx*4 .. tx*4+3
    const int ty  = tid >> 5;       // row group: rows ty*8 .. ty*8+7
    const int row0 = blockIdx.x * 64;

    unsigned long long acc[4][4];   // [row-pair][col]
#pragma unroll
    for (int p = 0; p < 4; ++p)
#pragma unroll
        for (int c = 0; c < 4; ++c) acc[p][c] = 0ull;

#pragma unroll 1
    for (int chunk = 0; chunk < 12; ++chunk) {
        const int sidx = chunk >> 2;          // 0: S1/Ww, 1: h/Wsw, 2: S2/Wtw
        const int k0   = (chunk & 3) * 32;
        const float* A = (sidx == 0) ? g_S1 : (sidx == 1) ? h : g_S2;
        const float* W = (sidx == 0) ? Ww   : (sidx == 1) ? Wsw : Wtw;

        __syncthreads();
        // load A tile: 64 rows x 32 k  (512 float4, 2 per thread)
#pragma unroll
        for (int j = 0; j < 2; ++j) {
            int lin = tid + j * 256;          // 0..511
            int r   = lin >> 3;               // 0..63
            int g   = lin & 7;                // float4 group in k
            float4 v = make_float4(0.f, 0.f, 0.f, 0.f);
            int row = row0 + r;
            if (row < N_NODES)
                v = *(const float4*)(A + (size_t)row * HIDDEN + k0 + g * 4);
            int kk = g * 4;
            As[kk + 0][r] = v.x;
            As[kk + 1][r] = v.y;
            As[kk + 2][r] = v.z;
            As[kk + 3][r] = v.w;
        }
        // load W tile: 128 cols x 32 k (1024 float4, 4 per thread)
#pragma unroll
        for (int j = 0; j < 4; ++j) {
            int lin = tid + j * 256;          // 0..1023
            int c   = lin >> 3;               // 0..127
            int g   = lin & 7;
            float4 v = *(const float4*)(W + (size_t)c * HIDDEN + k0 + g * 4);
            int kk = g * 4;
            Ws[kk + 0][c] = v.x;
            Ws[kk + 1][c] = v.y;
            Ws[kk + 2][c] = v.z;
            Ws[kk + 3][c] = v.w;
        }
        __syncthreads();

#pragma unroll
        for (int kk = 0; kk < 32; ++kk) {
            // 8 A rows as 4 packed pairs (128-bit smem loads, already packed)
            ulonglong2 a01 = *(const ulonglong2*)&As[kk][ty * 8];
            ulonglong2 a23 = *(const ulonglong2*)&As[kk][ty * 8 + 4];
            float4 w = *(const float4*)&Ws[kk][tx * 4];
            unsigned long long w0 = pack2(w.x, w.x);
            unsigned long long w1 = pack2(w.y, w.y);
            unsigned long long w2 = pack2(w.z, w.z);
            unsigned long long w3 = pack2(w.w, w.w);

            fma2(acc[0][0], a01.x, w0); fma2(acc[0][1], a01.x, w1);
            fma2(acc[0][2], a01.x, w2); fma2(acc[0][3], a01.x, w3);
            fma2(acc[1][0], a01.y, w0); fma2(acc[1][1], a01.y, w1);
            fma2(acc[1][2], a01.y, w2); fma2(acc[1][3], a01.y, w3);
            fma2(acc[2][0], a23.x, w0); fma2(acc[2][1], a23.x, w1);
            fma2(acc[2][2], a23.x, w2); fma2(acc[2][3], a23.x, w3);
            fma2(acc[3][0], a23.y, w0); fma2(acc[3][1], a23.y, w1);
            fma2(acc[3][2], a23.y, w2); fma2(acc[3][3], a23.y, w3);
        }
    }

    // epilogue: bias (degree-scaled) + relu, float4 stores
    const int colbase = tx * 4;
    float4 bw  = *(const float4*)(Wb  + colbase);
    float4 bs  = *(const float4*)(Wsb + colbase);
    float4 bt  = *(const float4*)(Wtb + colbase);

#pragma unroll
    for (int p = 0; p < 4; ++p) {
        int re = row0 + ty * 8 + 2 * p;
        if (re >= N_NODES) break;
        float2 v0 = unpack2(acc[p][0]);
        float2 v1 = unpack2(acc[p][1]);
        float2 v2 = unpack2(acc[p][2]);
        float2 v3 = unpack2(acc[p][3]);

        {
            float f1 = (float)g_d1[re];
            float f2 = (float)g_d2[re];
            float4 o;
            o.x = fmaxf(v0.x + f1 * bw.x + bs.x + f2 * bt.x, 0.f);
            o.y = fmaxf(v1.x + f1 * bw.y + bs.y + f2 * bt.y, 0.f);
            o.z = fmaxf(v2.x + f1 * bw.z + bs.z + f2 * bt.z, 0.f);
            o.w = fmaxf(v3.x + f1 * bw.w + bs.w + f2 * bt.w, 0.f);
            *(float4*)(out + (size_t)re * HIDDEN + colbase) = o;
        }
        int ro = re + 1;
        if (ro < N_NODES) {
            float f1 = (float)g_d1[ro];
            float f2 = (float)g_d2[ro];
            float4 o;
            o.x = fmaxf(v0.y + f1 * bw.x + bs.x + f2 * bt.x, 0.f);
            o.y = fmaxf(v1.y + f1 * bw.y + bs.y + f2 * bt.y, 0.f);
            o.z = fmaxf(v2.y + f1 * bw.z + bs.z + f2 * bt.z, 0.f);
            o.w = fmaxf(v3.y + f1 * bw.w + bs.w + f2 * bt.w, 0.f);
            *(float4*)(out + (size_t)ro * HIDDEN + colbase) = o;
        }
    }
}

// ---------------- launch -----------------------------------------------------
extern "C" void kernel_launch(void* const* d_in, const int* in_sizes, int n_in,
                              void* d_out, int out_size) {
    const float* h    = (const float*)d_in[0];
    const int*   esrc = (const int*)  d_in[1];
    const int*   edst = (const int*)  d_in[2];
    const float* Ww   = (const float*)d_in[3];
    const float* Wb   = (const float*)d_in[4];
    const float* Wsw  = (const float*)d_in[5];
    const float* Wsb  = (const float*)d_in[6];
    const float* Wtw  = (const float*)d_in[7];
    const float* Wtb  = (const float*)d_in[8];
    float* out = (float*)d_out;

    // resolve device-global scratch addresses once (host-side statics; the
    // lookups are pure address queries, no device work, no allocation)
    static void* p_S1 = nullptr;
    static void* p_S2 = nullptr;
    static void* p_d1 = nullptr;
    static void* p_d2 = nullptr;
    if (p_S1 == nullptr) {
        cudaGetSymbolAddress(&p_S1, g_S1);
        cudaGetSymbolAddress(&p_S2, g_S2);
        cudaGetSymbolAddress(&p_d1, g_d1);
        cudaGetSymbolAddress(&p_d2, g_d2);
    }

    // zero scratch via memset nodes (graph-capturable, full write bandwidth)
    cudaMemsetAsync(p_S1, 0, (size_t)N_NODES * HIDDEN * sizeof(float), 0);
    cudaMemsetAsync(p_S2, 0, (size_t)N_NODES * HIDDEN * sizeof(float), 0);
    cudaMemsetAsync(p_d1, 0, (size_t)N_NODES * sizeof(int), 0);
    cudaMemsetAsync(p_d2, 0, (size_t)N_NODES * sizeof(int), 0);

    edge_kernel<<<(N_EDGES + 7) / 8, 256>>>(h, esrc, edst);
    gemm_kernel<<<(N_NODES + 63) / 64, 256>>>(h, Ww, Wb, Wsw, Wsb, Wtw, Wtb, out);
}

// round 14
// speedup vs baseline: 1.1167x; 1.0104x over previous
#include <cuda_runtime.h>
#include <stdint.h>

#define N_NODES 100000
#define N_EDGES 800000
#define HIDDEN  128

// ---------------- scratch (static device memory; no allocation) -------------
__device__ float g_S1[(size_t)N_NODES * HIDDEN];   // sum over edges (i,j) of h[j], indexed by i
__device__ float g_S2[(size_t)N_NODES * HIDDEN];   // sum over edges (i,j) of h[i], indexed by j
__device__ int   g_d1[N_NODES];                    // out-degree
__device__ int   g_d2[N_NODES];                    // in-degree

// ---------------- helpers ---------------------------------------------------
__device__ __forceinline__ unsigned long long pack2(float lo, float hi) {
    unsigned long long r;
    asm("mov.b64 %0, {%1, %2};" : "=l"(r) : "f"(lo), "f"(hi));
    return r;
}
__device__ __forceinline__ float2 unpack2(unsigned long long v) {
    float2 f;
    asm("mov.b64 {%0, %1}, %2;" : "=f"(f.x), "=f"(f.y) : "l"(v));
    return f;
}
__device__ __forceinline__ void fma2(unsigned long long& acc,
                                     unsigned long long a,
                                     unsigned long long b) {
    asm("fma.rn.f32x2 %0, %1, %2, %0;" : "+l"(acc) : "l"(a), "l"(b));
}

// ---------------- kernel 0: zero scratch (measured 16.3us) ------------------
__global__ void zero_kernel() {
    size_t tid    = (size_t)blockIdx.x * blockDim.x + threadIdx.x;
    size_t stride = (size_t)gridDim.x * blockDim.x;
    const size_t n4 = (size_t)N_NODES * HIDDEN / 4;
    float4 z = make_float4(0.f, 0.f, 0.f, 0.f);
    for (size_t j = tid; j < n4; j += stride) {
        ((float4*)g_S1)[j] = z;
        ((float4*)g_S2)[j] = z;
    }
    for (size_t j = tid; j < N_NODES; j += stride) {
        g_d1[j] = 0;
        g_d2[j] = 0;
    }
}

// ---------------- kernel 1: fused edge aggregation (one warp per edge) ------
__global__ void __launch_bounds__(256) edge_kernel(const float* __restrict__ h,
                                                   const int*   __restrict__ esrc,
                                                   const int*   __restrict__ edst) {
    int warp = (blockIdx.x * blockDim.x + threadIdx.x) >> 5;
    int lane = threadIdx.x & 31;
    if (warp >= N_EDGES) return;

    int s = esrc[warp];
    int d = edst[warp];

    // gather h[d], h[s]  (32 lanes x float4 = 128 floats each)
    float4 vd = ((const float4*)(h + (size_t)d * HIDDEN))[lane];
    float4 vs = ((const float4*)(h + (size_t)s * HIDDEN))[lane];

    // scatter-add with vector atomics (sm_90+)
    atomicAdd(((float4*)(g_S1 + (size_t)s * HIDDEN)) + lane, vd);
    atomicAdd(((float4*)(g_S2 + (size_t)d * HIDDEN)) + lane, vs);

    if (lane == 0)      atomicAdd(&g_d1[s], 1);
    else if (lane == 1) atomicAdd(&g_d2[d], 1);
}

// ---------------- kernel 2: fused GEMM + bias + relu ------------------------
// out[i] = relu( S1[i]@Ww^T + d1[i]*Wb + h[i]@Wsw^T + Wsb + S2[i]@Wtw^T + d2[i]*Wtb )
// Tile: 64 rows x 128 cols per block, 256 threads, thread tile 8 rows x 4 cols.
// Accumulators are f32x2 pairs over adjacent rows -> fma.rn.f32x2.
// MEASURED BEST: this exact source compiles to 80 regs -> 3 CTAs/SM,
// occ 34.4%, 231.7us. Do not restructure; do not add prefetch registers.
__global__ void __launch_bounds__(256) gemm_kernel(const float* __restrict__ h,
                                                   const float* __restrict__ Ww,
                                                   const float* __restrict__ Wb,
                                                   const float* __restrict__ Wsw,
                                                   const float* __restrict__ Wsb,
                                                   const float* __restrict__ Wtw,
                                                   const float* __restrict__ Wtb,
                                                   float* __restrict__ out) {
    __shared__ float As[32][68];    // [k][row]
    __shared__ float Ws[32][132];   // [k][col]

    const int tid = threadIdx.x;
    const int tx  = tid & 31;       // col group: cols tx*4 .. tx*4+3
    const int ty  = tid >> 5;       // row group: rows ty*8 .. ty*8+7
    const int row0 = blockIdx.x * 64;

    unsigned long long acc[4][4];   // [row-pair][col]
#pragma unroll
    for (int p = 0; p < 4; ++p)
#pragma unroll
        for (int c = 0; c < 4; ++c) acc[p][c] = 0ull;

#pragma unroll 1
    for (int chunk = 0; chunk < 12; ++chunk) {
        const int sidx = chunk >> 2;          // 0: S1/Ww, 1: h/Wsw, 2: S2/Wtw
        const int k0   = (chunk & 3) * 32;
        const float* A = (sidx == 0) ? g_S1 : (sidx == 1) ? h : g_S2;
        const float* W = (sidx == 0) ? Ww   : (sidx == 1) ? Wsw : Wtw;

        __syncthreads();
        // load A tile: 64 rows x 32 k  (512 float4, 2 per thread)
#pragma unroll
        for (int j = 0; j < 2; ++j) {
            int lin = tid + j * 256;          // 0..511
            int r   = lin >> 3;               // 0..63
            int g   = lin & 7;                // float4 group in k
            float4 v = make_float4(0.f, 0.f, 0.f, 0.f);
            int row = row0 + r;
            if (row < N_NODES)
                v = *(const float4*)(A + (size_t)row * HIDDEN + k0 + g * 4);
            int kk = g * 4;
            As[kk + 0][r] = v.x;
            As[kk + 1][r] = v.y;
            As[kk + 2][r] = v.z;
            As[kk + 3][r] = v.w;
        }
        // load W tile: 128 cols x 32 k (1024 float4, 4 per thread)
#pragma unroll
        for (int j = 0; j < 4; ++j) {
            int lin = tid + j * 256;          // 0..1023
            int c   = lin >> 3;               // 0..127
            int g   = lin & 7;
            float4 v = *(const float4*)(W + (size_t)c * HIDDEN + k0 + g * 4);
            int kk = g * 4;
            Ws[kk + 0][c] = v.x;
            Ws[kk + 1][c] = v.y;
            Ws[kk + 2][c] = v.z;
            Ws[kk + 3][c] = v.w;
        }
        __syncthreads();

#pragma unroll
        for (int kk = 0; kk < 32; ++kk) {
            // 8 A rows as 4 packed pairs (128-bit smem loads, already packed)
            ulonglong2 a01 = *(const ulonglong2*)&As[kk][ty * 8];
            ulonglong2 a23 = *(const ulonglong2*)&As[kk][ty * 8 + 4];
            float4 w = *(const float4*)&Ws[kk][tx * 4];
            unsigned long long w0 = pack2(w.x, w.x);
            unsigned long long w1 = pack2(w.y, w.y);
            unsigned long long w2 = pack2(w.z, w.z);
            unsigned long long w3 = pack2(w.w, w.w);

            fma2(acc[0][0], a01.x, w0); fma2(acc[0][1], a01.x, w1);
            fma2(acc[0][2], a01.x, w2); fma2(acc[0][3], a01.x, w3);
            fma2(acc[1][0], a01.y, w0); fma2(acc[1][1], a01.y, w1);
            fma2(acc[1][2], a01.y, w2); fma2(acc[1][3], a01.y, w3);
            fma2(acc[2][0], a23.x, w0); fma2(acc[2][1], a23.x, w1);
            fma2(acc[2][2], a23.x, w2); fma2(acc[2][3], a23.x, w3);
            fma2(acc[3][0], a23.y, w0); fma2(acc[3][1], a23.y, w1);
            fma2(acc[3][2], a23.y, w2); fma2(acc[3][3], a23.y, w3);
        }
    }

    // epilogue: bias (degree-scaled) + relu, float4 stores
    const int colbase = tx * 4;
    float4 bw  = *(const float4*)(Wb  + colbase);
    float4 bs  = *(const float4*)(Wsb + colbase);
    float4 bt  = *(const float4*)(Wtb + colbase);

#pragma unroll
    for (int p = 0; p < 4; ++p) {
        int re = row0 + ty * 8 + 2 * p;
        if (re >= N_NODES) break;
        float2 v0 = unpack2(acc[p][0]);
        float2 v1 = unpack2(acc[p][1]);
        float2 v2 = unpack2(acc[p][2]);
        float2 v3 = unpack2(acc[p][3]);

        {
            float f1 = (float)g_d1[re];
            float f2 = (float)g_d2[re];
            float4 o;
            o.x = fmaxf(v0.x + f1 * bw.x + bs.x + f2 * bt.x, 0.f);
            o.y = fmaxf(v1.x + f1 * bw.y + bs.y + f2 * bt.y, 0.f);
            o.z = fmaxf(v2.x + f1 * bw.z + bs.z + f2 * bt.z, 0.f);
            o.w = fmaxf(v3.x + f1 * bw.w + bs.w + f2 * bt.w, 0.f);
            *(float4*)(out + (size_t)re * HIDDEN + colbase) = o;
        }
        int ro = re + 1;
        if (ro < N_NODES) {
            float f1 = (float)g_d1[ro];
            float f2 = (float)g_d2[ro];
            float4 o;
            o.x = fmaxf(v0.y + f1 * bw.x + bs.x + f2 * bt.x, 0.f);
            o.y = fmaxf(v1.y + f1 * bw.y + bs.y + f2 * bt.y, 0.f);
            o.z = fmaxf(v2.y + f1 * bw.z + bs.z + f2 * bt.z, 0.f);
            o.w = fmaxf(v3.y + f1 * bw.w + bs.w + f2 * bt.w, 0.f);
            *(float4*)(out + (size_t)ro * HIDDEN + colbase) = o;
        }
    }
}

// ---------------- launch -----------------------------------------------------
extern "C" void kernel_launch(void* const* d_in, const int* in_sizes, int n_in,
                              void* d_out, int out_size) {
    const float* h    = (const float*)d_in[0];
    const int*   esrc = (const int*)  d_in[1];
    const int*   edst = (const int*)  d_in[2];
    const float* Ww   = (const float*)d_in[3];
    const float* Wb   = (const float*)d_in[4];
    const float* Wsw  = (const float*)d_in[5];
    const float* Wsb  = (const float*)d_in[6];
    const float* Wtw  = (const float*)d_in[7];
    const float* Wtb  = (const float*)d_in[8];
    float* out = (float*)d_out;

    zero_kernel<<<2048, 256>>>();
    edge_kernel<<<(N_EDGES + 7) / 8, 256>>>(h, esrc, edst);
    gemm_kernel<<<(N_NODES + 63) / 64, 256>>>(h, Ww, Wb, Wsw, Wsb, Wtw, Wtb, out);
}